// round 9
// baseline (speedup 1.0000x reference)
#include <cuda_runtime.h>
#include <cuda_bf16.h>

// Problem constants: input shape (N=4, C=3, 128,128,128), fp32.
#define S_SPATIAL (128 * 128 * 128)          // 2,097,152 contiguous elems per (n,c) segment
#define N_BATCH   4
#define C_CHAN    3
#define N_SEG     (N_BATCH * C_CHAN)          // 12 contiguous segments
#define M_PER_CH  ((long long)N_BATCH * S_SPATIAL)   // 8,388,608 elems per channel

#define BLOCKS_PER_SEG 64
#define THREADS        256
#define SLOTS_PER_CH   (N_BATCH * BLOCKS_PER_SEG)    // 256 partials per channel
#define TOTAL_BLOCKS   (N_SEG * BLOCKS_PER_SEG)      // 768
#define ELEMS_PER_BLK  (S_SPATIAL / BLOCKS_PER_SEG)  // 32768
#define VEC4_PER_BLK   (ELEMS_PER_BLK / 4)           // 8192

// Per-block partials, channel-major: slot = c * 256 + (n * 64 + chunk).
// Every slot is overwritten on every launch -> no init pass required.
__device__ float    g_psum[C_CHAN * SLOTS_PER_CH];
__device__ int      g_pcnt[C_CHAN * SLOTS_PER_CH];
// Arrival counter: starts 0 at module load; last block resets it to 0 each
// launch, so graph replays are deterministic with no init kernel.
__device__ unsigned g_arrive = 0u;

__global__ __launch_bounds__(THREADS) void bce_fused_kernel(
    const float* __restrict__ p_in,
    const float* __restrict__ t_in,
    float* __restrict__ out)
{
    const int seg   = blockIdx.x >> 6;        // 0..11
    const int chunk = blockIdx.x & 63;
    const int c     = seg % C_CHAN;           // channel, uniform per block
    const int n     = seg / C_CHAN;           // batch index

    const size_t base = (size_t)seg * S_SPATIAL + (size_t)chunk * ELEMS_PER_BLK;
    const float4* __restrict__ p4 = (const float4*)(p_in + base);
    const float4* __restrict__ t4 = (const float4*)(t_in + base);

    float sum = 0.0f;
    int   cnt = 0;

    #pragma unroll 4
    for (int i = threadIdx.x; i < VEC4_PER_BLK; i += THREADS) {
        float4 pv = p4[i];
        float4 tv = t4[i];
        {
            bool one = (tv.x != 0.0f);
            float x = one ? pv.x : (1.0f - pv.x);
            sum += fmaxf(__logf(x), -100.0f);
            cnt += one;
        }
        {
            bool one = (tv.y != 0.0f);
            float x = one ? pv.y : (1.0f - pv.y);
            sum += fmaxf(__logf(x), -100.0f);
            cnt += one;
        }
        {
            bool one = (tv.z != 0.0f);
            float x = one ? pv.z : (1.0f - pv.z);
            sum += fmaxf(__logf(x), -100.0f);
            cnt += one;
        }
        {
            bool one = (tv.w != 0.0f);
            float x = one ? pv.w : (1.0f - pv.w);
            sum += fmaxf(__logf(x), -100.0f);
            cnt += one;
        }
    }

    // Warp reduction
    #pragma unroll
    for (int off = 16; off > 0; off >>= 1) {
        sum += __shfl_xor_sync(0xFFFFFFFFu, sum, off);
        cnt += __shfl_xor_sync(0xFFFFFFFFu, cnt, off);
    }

    // Block reduction across 8 warps
    __shared__ float s_sum[THREADS / 32];
    __shared__ int   s_cnt[THREADS / 32];
    __shared__ bool  s_last;
    const int wid = threadIdx.x >> 5;
    const int lid = threadIdx.x & 31;
    if (lid == 0) {
        s_sum[wid] = sum;
        s_cnt[wid] = cnt;
    }
    __syncthreads();

    if (threadIdx.x == 0) {
        float bsum = 0.0f;
        int   bcnt = 0;
        #pragma unroll
        for (int w = 0; w < THREADS / 32; w++) {
            bsum += s_sum[w];
            bcnt += s_cnt[w];
        }
        const int slot = c * SLOTS_PER_CH + n * BLOCKS_PER_SEG + chunk;
        g_psum[slot] = bsum;
        g_pcnt[slot] = bcnt;
        __threadfence();                         // publish partials device-wide
        unsigned prev = atomicAdd(&g_arrive, 1u);
        s_last = (prev == TOTAL_BLOCKS - 1);
    }
    __syncthreads();

    if (!s_last) return;

    // ---- Last block: reduce 768 partials (3 channels x 256 slots) ----
    const int tid = threadIdx.x;                 // 0..255, one slot per channel
    double ds0 = (double)g_psum[0 * SLOTS_PER_CH + tid];
    double ds1 = (double)g_psum[1 * SLOTS_PER_CH + tid];
    double ds2 = (double)g_psum[2 * SLOTS_PER_CH + tid];
    int    dc0 = g_pcnt[0 * SLOTS_PER_CH + tid];
    int    dc1 = g_pcnt[1 * SLOTS_PER_CH + tid];
    int    dc2 = g_pcnt[2 * SLOTS_PER_CH + tid];

    #pragma unroll
    for (int off = 16; off > 0; off >>= 1) {
        ds0 += __shfl_xor_sync(0xFFFFFFFFu, ds0, off);
        ds1 += __shfl_xor_sync(0xFFFFFFFFu, ds1, off);
        ds2 += __shfl_xor_sync(0xFFFFFFFFu, ds2, off);
        dc0 += __shfl_xor_sync(0xFFFFFFFFu, dc0, off);
        dc1 += __shfl_xor_sync(0xFFFFFFFFu, dc1, off);
        dc2 += __shfl_xor_sync(0xFFFFFFFFu, dc2, off);
    }

    __shared__ double f_sum[3][THREADS / 32];
    __shared__ int    f_cnt[3][THREADS / 32];
    if (lid == 0) {
        f_sum[0][wid] = ds0; f_sum[1][wid] = ds1; f_sum[2][wid] = ds2;
        f_cnt[0][wid] = dc0; f_cnt[1][wid] = dc1; f_cnt[2][wid] = dc2;
    }
    __syncthreads();

    if (threadIdx.x == 0) {
        double total = 0.0;
        #pragma unroll
        for (int ch = 0; ch < C_CHAN; ch++) {
            double s = 0.0;
            long long ones = 0;
            #pragma unroll
            for (int w = 0; w < THREADS / 32; w++) {
                s    += f_sum[ch][w];
                ones += f_cnt[ch][w];
            }
            double bce = -s / (double)M_PER_CH;
            double wgt = (ones > 0) ? ((double)M_PER_CH / (double)ones)
                                    : 1000.0;   // EMPTY_WEIGHT
            total += wgt * bce;
        }
        out[0] = (float)(total / (double)C_CHAN);
        g_arrive = 0u;                           // self-reset for next replay
    }
}

extern "C" void kernel_launch(void* const* d_in, const int* in_sizes, int n_in,
                              void* d_out, int out_size) {
    const float* input  = (const float*)d_in[0];
    const float* target = (const float*)d_in[1];
    float* out = (float*)d_out;

    bce_fused_kernel<<<TOTAL_BLOCKS, THREADS>>>(input, target, out);
}